// round 14
// baseline (speedup 1.0000x reference)
#include <cuda_runtime.h>
#include <cuda_bf16.h>
#include <cstdint>

#define NPTS 16384
#define ODIM 128
#define KNN  16
#define NC   512           // candidate buffer per query (4 x 128 quarters)
#define NBLK 128           // 16384 / 128
#define STILES 16          // subsample tiles total (2 halves x 8)
#define JSPLIT 4
#define JT_PER 32

// ---------------- scratch (no allocation allowed) ----------------
__device__ float g_base[NPTS * ODIM];              // x @ (W1a - W1b) + b1
__device__ float g_Bv[NPTS * ODIM];                // x @ W1b
__device__ __align__(16) float g_sq[NPTS];         // |x|^2
__device__ float g_tau[NPTS * 2];                  // per-(query,half) threshold
__device__ int   g_idx[NPTS * KNN];                // final knn indices
__device__ int   g_cnt[NPTS * 4];                  // counts per (query, slice)
__device__ int   g_cand[NPTS * NC];                // candidate indices
__device__ __align__(16) unsigned g_Af[NBLK * 4096];  // A fragments (bf16 hi)
__device__ __align__(16) unsigned g_Bf[NBLK * 4096];  // B fragments (bf16 hi)

// =================================================================
// precompute: base, Bv, sq.  4 points per block, 128 threads (o=tid)
// =================================================================
__global__ void __launch_bounds__(128) precompute_kernel(
    const float* __restrict__ x, const float* __restrict__ W1,
    const float* __restrict__ b1)
{
    const int n0  = blockIdx.x * 4;
    const int tid = threadIdx.x;
    __shared__ float xs[4][64];

    #pragma unroll
    for (int r = 0; r < 2; r++) {
        int li = r * 128 + tid;
        xs[li >> 6][li & 63] = x[n0 * 64 + li];
    }
    __syncthreads();

    float a1[4] = {0.f, 0.f, 0.f, 0.f};
    float a2[4] = {0.f, 0.f, 0.f, 0.f};
    #pragma unroll 4
    for (int c = 0; c < 64; c++) {
        float wa = W1[c * 128 + tid];
        float wb = W1[(64 + c) * 128 + tid];
        float wd = wa - wb;
        #pragma unroll
        for (int nn = 0; nn < 4; nn++) {
            float xv = xs[nn][c];
            a1[nn] = fmaf(xv, wd, a1[nn]);
            a2[nn] = fmaf(xv, wb, a2[nn]);
        }
    }
    float bb = b1[tid];
    #pragma unroll
    for (int nn = 0; nn < 4; nn++) {
        g_base[(n0 + nn) * 128 + tid] = a1[nn] + bb;
        g_Bv[(n0 + nn) * 128 + tid]  = a2[nn];
    }

    int w = tid >> 5, lane = tid & 31;
    float v = xs[w][lane] * xs[w][lane] + xs[w][lane + 32] * xs[w][lane + 32];
    #pragma unroll
    for (int off = 16; off > 0; off >>= 1)
        v += __shfl_xor_sync(0xffffffffu, v, off);
    if (lane == 0) g_sq[n0 + w] = v;
}

// =================================================================
// fragpack: bf16(hi) of x into mma fragment order (per 128-pt block).
// =================================================================
__global__ void __launch_bounds__(256) fragpack_kernel(const float* __restrict__ x)
{
    __shared__ unsigned sA[4096];
    __shared__ unsigned sB[4096];

    const int blk = blockIdx.x;
    const int tid = threadIdx.x;
    const int rl  = tid >> 1;
    const int c0  = (tid & 1) * 32;

    float v[32];
    const float4* xr = (const float4*)(x + (blk * 128 + rl) * 64 + c0);
    #pragma unroll
    for (int i = 0; i < 8; i++) {
        float4 t = xr[i];
        v[i * 4 + 0] = t.x; v[i * 4 + 1] = t.y;
        v[i * 4 + 2] = t.z; v[i * 4 + 3] = t.w;
    }

    const int mt = rl >> 4, gid = rl & 7, r0 = (rl >> 3) & 1;
    const int nt = rl >> 3;
    const int l  = gid * 4;

    #pragma unroll
    for (int cc = 0; cc < 32; cc += 2) {
        int c = c0 + cc;
        __nv_bfloat16 h0 = __float2bfloat16(v[cc]);
        __nv_bfloat16 h1 = __float2bfloat16(v[cc + 1]);
        unsigned uhi = ((unsigned)__bfloat16_as_ushort(h1) << 16) | __bfloat16_as_ushort(h0);

        int ks = c >> 4, cb = (c >> 1) & 3, r1 = (c >> 3) & 1;
        int la = l + cb;
        int rA = r1 * 2 + r0;
        sA[(ks * 8 + mt) * 128 + la * 4 + rA] = uhi;
        sB[(ks * 16 + nt) * 64 + la * 2 + r1] = uhi;
    }
    __syncthreads();

    uint4* dA = (uint4*)(g_Af + blk * 4096);
    uint4* dB = (uint4*)(g_Bf + blk * 4096);
    const uint4* s4A = (const uint4*)sA;
    const uint4* s4B = (const uint4*)sB;
    #pragma unroll
    for (int i = 0; i < 4; i++) {
        dA[i * 256 + tid] = s4A[i * 256 + tid];
        dB[i * 256 + tid] = s4B[i * 256 + tid];
    }
}

// =================================================================
// tau_kernel: exact top-16 over an 8-tile subsample -> g_tau.
// CTA = (qblk, half): 256 CTAs.  tau = min over halves (done in scan).
// =================================================================
#define T_OFF_B   4096           // 2 x 4096 u32
#define T_OFF_SQ  12288          // 2 x 128 floats
#define T_OFF_MRG 12544          // 128 x 64 floats
#define T_SM_U32  20736
#define T_SM_BYTES (T_SM_U32 * 4)

#define RIPPLE(kd, ki, dval, jval) do {                                    \
    float _td = (dval); int _tj = (jval);                                  \
    _Pragma("unroll")                                                      \
    for (int _m = 0; _m < 16; _m++) {                                      \
        bool _p = _td < kd[_m];                                            \
        float _ok = kd[_m]; int _oj = ki[_m];                              \
        kd[_m] = _p ? _td : _ok;                                           \
        ki[_m] = _p ? _tj : _oj;                                           \
        _td = _p ? _ok : _td;                                              \
        _tj = _p ? _oj : _tj;                                              \
    }                                                                      \
} while (0)

__device__ __forceinline__ void cp16(unsigned saddr, const void* g)
{
    asm volatile("cp.async.cg.shared.global [%0], [%1], 16;" :: "r"(saddr), "l"(g));
}

__global__ void __launch_bounds__(256, 1) tau_kernel()
{
    extern __shared__ __align__(16) unsigned sm[];
    float* mrgf = (float*)(sm + T_OFF_MRG);

    const int tid  = threadIdx.x;
    const int lane = tid & 31;
    const int wid  = tid >> 5;
    const int g    = lane >> 2;
    const int c    = lane & 3;
    const int qblk = blockIdx.x >> 1;
    const int half = blockIdx.x & 1;
    const int jt0  = half * (STILES / 2);
    const int jt1  = jt0 + STILES / 2;
    const unsigned smbase = (unsigned)__cvta_generic_to_shared(sm);

    {
        const uint4* gA = (const uint4*)(g_Af + qblk * 4096);
        #pragma unroll
        for (int i = 0; i < 4; i++)
            cp16(smbase + (i * 256 + tid) * 16, gA + i * 256 + tid);
        const uint4* gB = (const uint4*)(g_Bf + jt0 * 4096);
        #pragma unroll
        for (int i = 0; i < 4; i++)
            cp16(smbase + (T_OFF_B + (jt0 & 1) * 4096 + i * 1024) * 4 + tid * 16,
                 gB + i * 256 + tid);
        if (tid < 32)
            cp16(smbase + (T_OFF_SQ + (jt0 & 1) * 128) * 4 + tid * 16,
                 g_sq + jt0 * 128 + tid * 4);
    }
    asm volatile("cp.async.commit_group;");

    float kd0[16], kd1[16]; int ki0[16], ki1[16];
    #pragma unroll
    for (int m = 0; m < 16; m++) {
        kd0[m] = 1e30f; ki0[m] = 0;
        kd1[m] = 1e30f; ki1[m] = 0;
    }

    for (int jt = jt0; jt < jt1; jt++) {
        const int cur = jt & 1;
        if (jt + 1 < jt1) {
            const uint4* gB = (const uint4*)(g_Bf + (jt + 1) * 4096);
            #pragma unroll
            for (int i = 0; i < 4; i++)
                cp16(smbase + (T_OFF_B + ((jt + 1) & 1) * 4096 + i * 1024) * 4 + tid * 16,
                     gB + i * 256 + tid);
            if (tid < 32)
                cp16(smbase + (T_OFF_SQ + ((jt + 1) & 1) * 128) * 4 + tid * 16,
                     g_sq + (jt + 1) * 128 + tid * 4);
        }
        asm volatile("cp.async.commit_group;");
        asm volatile("cp.async.wait_group 1;");
        __syncthreads();

        unsigned a[4][4];
        #pragma unroll
        for (int ks = 0; ks < 4; ks++) {
            uint4 t = *(const uint4*)(sm + (ks * 8 + wid) * 128 + lane * 4);
            a[ks][0] = t.x; a[ks][1] = t.y; a[ks][2] = t.z; a[ks][3] = t.w;
        }
        const float* sqb = (const float*)(sm + T_OFF_SQ + cur * 128);
        const unsigned* Bb = sm + T_OFF_B + cur * 4096;

        #pragma unroll 4
        for (int ni = 0; ni < 16; ni++) {
            unsigned b[4][2];
            #pragma unroll
            for (int ks = 0; ks < 4; ks++) {
                uint2 t = *(const uint2*)(Bb + (ks * 16 + ni) * 64 + lane * 2);
                b[ks][0] = t.x; b[ks][1] = t.y;
            }
            float acc[4] = {0.f, 0.f, 0.f, 0.f};
            #pragma unroll
            for (int ks = 0; ks < 4; ks++)
                asm volatile(
                    "mma.sync.aligned.m16n8k16.row.col.f32.bf16.bf16.f32 "
                    "{%0,%1,%2,%3}, {%4,%5,%6,%7}, {%8,%9}, {%0,%1,%2,%3};"
                    : "+f"(acc[0]), "+f"(acc[1]), "+f"(acc[2]), "+f"(acc[3])
                    : "r"(a[ks][0]), "r"(a[ks][1]), "r"(a[ks][2]), "r"(a[ks][3]),
                      "r"(b[ks][0]), "r"(b[ks][1]));

            float2 q = *(const float2*)&sqb[ni * 8 + c * 2];
            float d0 = fmaf(0.5f, q.x, -acc[0]);
            float d1 = fmaf(0.5f, q.y, -acc[1]);
            float d2 = fmaf(0.5f, q.x, -acc[2]);
            float d3 = fmaf(0.5f, q.y, -acc[3]);
            int jb = jt * 128 + ni * 8 + c * 2;
            if (fminf(d0, d1) < kd0[15]) {
                RIPPLE(kd0, ki0, d0, jb);
                RIPPLE(kd0, ki0, d1, jb + 1);
            }
            if (fminf(d2, d3) < kd1[15]) {
                RIPPLE(kd1, ki1, d2, jb);
                RIPPLE(kd1, ki1, d3, jb + 1);
            }
        }
        __syncthreads();
    }

    // merge 4 sorted lane-lists -> 16th smallest -> g_tau[(q,half)]
    {
        const int rowA = wid * 16 + g;
        #pragma unroll
        for (int m = 0; m < 16; m++) {
            mrgf[rowA * 64 + c * 16 + m] = kd0[m];
            mrgf[(rowA + 8) * 64 + c * 16 + m] = kd1[m];
        }
    }
    __syncthreads();
    if (tid < 128) {
        const float* basep = mrgf + tid * 64;
        int p0 = 0, p1 = 0, p2 = 0, p3 = 0;
        float last = 1e30f;
        #pragma unroll
        for (int m = 0; m < 16; m++) {
            float v0 = basep[p0];
            float v1 = basep[16 + p1];
            float v2 = basep[32 + p2];
            float v3 = basep[48 + p3];
            float mn01 = fminf(v0, v1), mn23 = fminf(v2, v3);
            last = fminf(mn01, mn23);
            if (v0 == last)      p0++;
            else if (v1 == last) p1++;
            else if (v2 == last) p2++;
            else                 p3++;
        }
        g_tau[(qblk * 128 + tid) * 2 + half] = last;
    }
}

// =================================================================
// scan_kernel: full scan, branch-free ballot compaction of d <= tau.
// CTA = (qblk, jslice): 128 queries x 32 tiles. 512 CTAs, ~3/SM.
// Slice s writes candidates into quarter s of g_cand (128 slots).
// =================================================================
#define S_OFF_B   4096           // 2 x 4096 u32
#define S_OFF_SQ  12288          // 2 x 128 floats
#define S_OFF_CNT 12544          // 128 ints
#define S_SM_U32  12672
#define S_SM_BYTES (S_SM_U32 * 4)

__global__ void __launch_bounds__(256, 3) scan_kernel()
{
    extern __shared__ __align__(16) unsigned sm[];
    int* scnt = (int*)(sm + S_OFF_CNT);

    const int tid  = threadIdx.x;
    const int lane = tid & 31;
    const int wid  = tid >> 5;
    const int g    = lane >> 2;
    const int c    = lane & 3;
    const int qblk   = blockIdx.x >> 2;
    const int jslice = blockIdx.x & 3;
    const int jt0 = jslice * JT_PER;
    const unsigned smbase = (unsigned)__cvta_generic_to_shared(sm);

    {
        const uint4* gA = (const uint4*)(g_Af + qblk * 4096);
        #pragma unroll
        for (int i = 0; i < 4; i++)
            cp16(smbase + (i * 256 + tid) * 16, gA + i * 256 + tid);
        const uint4* gB = (const uint4*)(g_Bf + jt0 * 4096);
        #pragma unroll
        for (int i = 0; i < 4; i++)
            cp16(smbase + (S_OFF_B + i * 1024) * 4 + tid * 16, gB + i * 256 + tid);
        if (tid < 32)
            cp16(smbase + S_OFF_SQ * 4 + tid * 16, g_sq + jt0 * 128 + tid * 4);
    }
    asm volatile("cp.async.commit_group;");

    if (tid < 128) scnt[tid] = 0;

    const int rowA = wid * 16 + g;
    const int rowB = rowA + 8;
    const int rowAg = qblk * 128 + rowA;
    const int rowBg = qblk * 128 + rowB;
    const float tg  = fminf(g_tau[rowAg * 2], g_tau[rowAg * 2 + 1]);
    const float tg8 = fminf(g_tau[rowBg * 2], g_tau[rowBg * 2 + 1]);
    const int sh4  = g * 4;
    const int cbase = jslice * 128;

    for (int jt = jt0; jt < jt0 + JT_PER; jt++) {
        const int cur = jt & 1;
        if (jt + 1 < jt0 + JT_PER) {
            const uint4* gB = (const uint4*)(g_Bf + (jt + 1) * 4096);
            #pragma unroll
            for (int i = 0; i < 4; i++)
                cp16(smbase + (S_OFF_B + ((jt + 1) & 1) * 4096 + i * 1024) * 4 + tid * 16,
                     gB + i * 256 + tid);
            if (tid < 32)
                cp16(smbase + (S_OFF_SQ + ((jt + 1) & 1) * 128) * 4 + tid * 16,
                     g_sq + (jt + 1) * 128 + tid * 4);
        }
        asm volatile("cp.async.commit_group;");
        asm volatile("cp.async.wait_group 1;");
        __syncthreads();

        unsigned a[4][4];
        #pragma unroll
        for (int ks = 0; ks < 4; ks++) {
            uint4 t = *(const uint4*)(sm + (ks * 8 + wid) * 128 + lane * 4);
            a[ks][0] = t.x; a[ks][1] = t.y; a[ks][2] = t.z; a[ks][3] = t.w;
        }
        const float* sqb = (const float*)(sm + S_OFF_SQ + cur * 128);
        const unsigned* Bb = sm + S_OFF_B + cur * 4096;

        #pragma unroll 4
        for (int ni = 0; ni < 16; ni++) {
            unsigned b[4][2];
            #pragma unroll
            for (int ks = 0; ks < 4; ks++) {
                uint2 t = *(const uint2*)(Bb + (ks * 16 + ni) * 64 + lane * 2);
                b[ks][0] = t.x; b[ks][1] = t.y;
            }
            float acc[4] = {0.f, 0.f, 0.f, 0.f};
            #pragma unroll
            for (int ks = 0; ks < 4; ks++)
                asm volatile(
                    "mma.sync.aligned.m16n8k16.row.col.f32.bf16.bf16.f32 "
                    "{%0,%1,%2,%3}, {%4,%5,%6,%7}, {%8,%9}, {%0,%1,%2,%3};"
                    : "+f"(acc[0]), "+f"(acc[1]), "+f"(acc[2]), "+f"(acc[3])
                    : "r"(a[ks][0]), "r"(a[ks][1]), "r"(a[ks][2]), "r"(a[ks][3]),
                      "r"(b[ks][0]), "r"(b[ks][1]));

            float2 q = *(const float2*)&sqb[ni * 8 + c * 2];
            float d0 = fmaf(0.5f, q.x, -acc[0]);
            float d1 = fmaf(0.5f, q.y, -acc[1]);
            float d2 = fmaf(0.5f, q.x, -acc[2]);
            float d3 = fmaf(0.5f, q.y, -acc[3]);
            bool c0 = d0 <= tg, c1 = d1 <= tg;
            bool c2 = d2 <= tg8, c3 = d3 <= tg8;
            unsigned bl0 = __ballot_sync(0xffffffffu, c0);
            unsigned bl1 = __ballot_sync(0xffffffffu, c1);
            unsigned bl2 = __ballot_sync(0xffffffffu, c2);
            unsigned bl3 = __ballot_sync(0xffffffffu, c3);
            if (bl0 | bl1 | bl2 | bl3) {       // warp-uniform
                unsigned h0 = (bl0 >> sh4) & 0xFu, h1 = (bl1 >> sh4) & 0xFu;
                unsigned h2 = (bl2 >> sh4) & 0xFu, h3 = (bl3 >> sh4) & 0xFu;
                int cntA = __popc(h0) + __popc(h1);
                int cntB = __popc(h2) + __popc(h3);
                int baseA = 0, baseB = 0;
                if (c == 0 && cntA) baseA = atomicAdd(&scnt[rowA], cntA);
                if (c == 0 && cntB) baseB = atomicAdd(&scnt[rowB], cntB);
                baseA = __shfl_sync(0xffffffffu, baseA, sh4);
                baseB = __shfl_sync(0xffffffffu, baseB, sh4);
                unsigned lm = (1u << c) - 1u;
                int jb = jt * 128 + ni * 8 + c * 2;
                int pA0 = baseA + __popc(h0 & lm);
                int pA1 = baseA + __popc(h0) + __popc(h1 & lm);
                int pB0 = baseB + __popc(h2 & lm);
                int pB1 = baseB + __popc(h2) + __popc(h3 & lm);
                if (c0 && pA0 < 128) g_cand[rowAg * NC + cbase + pA0] = jb;
                if (c1 && pA1 < 128) g_cand[rowAg * NC + cbase + pA1] = jb + 1;
                if (c2 && pB0 < 128) g_cand[rowBg * NC + cbase + pB0] = jb;
                if (c3 && pB1 < 128) g_cand[rowBg * NC + cbase + pB1] = jb + 1;
            }
        }
        __syncthreads();
    }

    if (tid < 128)
        g_cnt[(qblk * 128 + tid) * 4 + jslice] = min(scnt[tid], 128);
}

// =================================================================
// refine: exact fp32 re-score of the candidate set, true top-16.
// 1 query per block, 256 threads; contiguous slots (2 per thread),
// inactive warps skip entirely.
// =================================================================
__global__ void __launch_bounds__(256) refine_kernel(const float* __restrict__ x)
{
    __shared__ float xi[64];
    __shared__ __align__(16) float ss[NC + 4];
    const int tid = threadIdx.x;
    const int q   = blockIdx.x;
    const int c0s = g_cnt[q * 4];
    const int c1s = g_cnt[q * 4 + 1];
    const int c2s = g_cnt[q * 4 + 2];
    const int c3s = g_cnt[q * 4 + 3];
    const int e0 = c0s, e1 = c0s + c1s, e2 = e1 + c2s;
    const int count = e2 + c3s;

    if (tid < 64) xi[tid] = x[q * 64 + tid];
    if (tid < 4)  ss[NC + tid] = 1e30f;
    __syncthreads();

    const int slot0 = tid * 2, slot1 = tid * 2 + 1;
    float s0 = 1e30f, s1 = 1e30f;
    int cj0 = 0, cj1 = 0;
    if (slot0 < count) {
        #pragma unroll
        for (int sl = 0; sl < 2; sl++) {
            int slot = slot0 + sl;
            if (slot < count) {
                int pos;
                if (slot < e0)      pos = slot;
                else if (slot < e1) pos = 128 + (slot - e0);
                else if (slot < e2) pos = 256 + (slot - e1);
                else                pos = 384 + (slot - e2);
                int cj = g_cand[q * NC + pos];
                const float4* xr = (const float4*)(x + cj * 64);
                float dot = 0.f;
                #pragma unroll
                for (int u = 0; u < 16; u++) {
                    float4 v = xr[u];
                    dot = fmaf(xi[u * 4 + 0], v.x, dot);
                    dot = fmaf(xi[u * 4 + 1], v.y, dot);
                    dot = fmaf(xi[u * 4 + 2], v.z, dot);
                    dot = fmaf(xi[u * 4 + 3], v.w, dot);
                }
                float s = fmaf(0.5f, g_sq[cj], -dot);
                if (sl == 0) { s0 = s; cj0 = cj; }
                else         { s1 = s; cj1 = cj; }
            }
        }
    }
    ss[slot0] = s0;
    ss[slot1] = s1;
    __syncthreads();

    if (slot0 < count) {                       // inactive warps skip
        const int nIter = (count + 3) >> 2;
        int rank0 = 0, rank1 = 0;
        #pragma unroll 4
        for (int m4 = 0; m4 < nIter; m4++) {
            float4 v = *(const float4*)&ss[m4 * 4];
            int b0 = m4 * 4;
            rank0 += (v.x < s0) || (v.x == s0 && b0 + 0 < slot0);
            rank0 += (v.y < s0) || (v.y == s0 && b0 + 1 < slot0);
            rank0 += (v.z < s0) || (v.z == s0 && b0 + 2 < slot0);
            rank0 += (v.w < s0) || (v.w == s0 && b0 + 3 < slot0);
            rank1 += (v.x < s1) || (v.x == s1 && b0 + 0 < slot1);
            rank1 += (v.y < s1) || (v.y == s1 && b0 + 1 < slot1);
            rank1 += (v.z < s1) || (v.z == s1 && b0 + 2 < slot1);
            rank1 += (v.w < s1) || (v.w == s1 && b0 + 3 < slot1);
        }
        if (rank0 < KNN) g_idx[q * KNN + rank0] = cj0;
        if (slot1 < count && rank1 < KNN) g_idx[q * KNN + rank1] = cj1;
    }
}

// =================================================================
// aggregate: s = mean_k relu(base + Bv[j_k]);  out = s @ W2 + b2
// 8 points per block, 128 threads (o = tid), W2 read coalesced.
// =================================================================
__global__ void __launch_bounds__(128) aggregate_kernel(
    const float* __restrict__ W2, const float* __restrict__ b2,
    float* __restrict__ out)
{
    const int n0  = blockIdx.x * 8;
    const int tid = threadIdx.x;
    __shared__ float ss[8][128];
    __shared__ int sidx[128];

    sidx[tid] = g_idx[n0 * 16 + tid];
    __syncthreads();

    #pragma unroll
    for (int p = 0; p < 8; p++) {
        float bv  = g_base[(n0 + p) * 128 + tid];
        float acc = 0.f;
        #pragma unroll
        for (int k = 0; k < 16; k++) {
            float v = bv + g_Bv[sidx[p * 16 + k] * 128 + tid];
            acc += fmaxf(v, 0.f);
        }
        ss[p][tid] = acc * (1.0f / 16.0f);
    }
    __syncthreads();

    float r[8];
    float bb = b2[tid];
    #pragma unroll
    for (int p = 0; p < 8; p++) r[p] = bb;

    #pragma unroll 4
    for (int i = 0; i < 128; i++) {
        float w = W2[i * 128 + tid];
        #pragma unroll
        for (int p = 0; p < 8; p++)
            r[p] = fmaf(ss[p][i], w, r[p]);
    }
    #pragma unroll
    for (int p = 0; p < 8; p++)
        out[(n0 + p) * 128 + tid] = r[p];
}

// =================================================================
extern "C" void kernel_launch(void* const* d_in, const int* in_sizes, int n_in,
                              void* d_out, int out_size)
{
    const float* x  = (const float*)d_in[0];
    const float* W1 = (const float*)d_in[1];
    const float* b1 = (const float*)d_in[2];
    const float* W2 = (const float*)d_in[3];
    const float* b2 = (const float*)d_in[4];
    float* out = (float*)d_out;

    cudaFuncSetAttribute(tau_kernel,
                         cudaFuncAttributeMaxDynamicSharedMemorySize, T_SM_BYTES);
    cudaFuncSetAttribute(scan_kernel,
                         cudaFuncAttributeMaxDynamicSharedMemorySize, S_SM_BYTES);

    precompute_kernel<<<NPTS / 4, 128>>>(x, W1, b1);
    fragpack_kernel<<<NBLK, 256>>>(x);
    tau_kernel<<<NBLK * 2, 256, T_SM_BYTES>>>();
    scan_kernel<<<NBLK * JSPLIT, 256, S_SM_BYTES>>>();
    refine_kernel<<<NPTS, 256>>>(x);
    aggregate_kernel<<<NPTS / 8, 128>>>(W2, b2, out);
}

// round 15
// speedup vs baseline: 1.0467x; 1.0467x over previous
#include <cuda_runtime.h>
#include <cuda_bf16.h>
#include <cstdint>

#define NPTS 16384
#define ODIM 128
#define KNN  16
#define NC   512           // candidate buffer per query (4 x 128 quarters)
#define NBLK 128           // 16384 / 128
#define STILES 16          // subsample tiles total (2 halves x 8)
#define JSPLIT 4
#define JT_PER 32

// ---------------- scratch (no allocation allowed) ----------------
__device__ float g_base[NPTS * ODIM];              // x @ (W1a - W1b) + b1
__device__ float g_Bv[NPTS * ODIM];                // x @ W1b
__device__ __align__(16) float g_sq[NPTS];         // |x|^2
__device__ float g_tau[NPTS * 2];                  // per-(query,half) threshold
__device__ int   g_idx[NPTS * KNN];                // final knn indices
__device__ int   g_cnt[NPTS * 4];                  // counts per (query, slice)
__device__ int   g_cand[NPTS * NC];                // candidate indices
__device__ __align__(16) unsigned g_Af[NBLK * 4096];  // A fragments (bf16 hi)
__device__ __align__(16) unsigned g_Bf[NBLK * 4096];  // B fragments (bf16 hi)

// =================================================================
// precompute: base, Bv, sq.  4 points per block, 128 threads (o=tid)
// =================================================================
__global__ void __launch_bounds__(128) precompute_kernel(
    const float* __restrict__ x, const float* __restrict__ W1,
    const float* __restrict__ b1)
{
    const int n0  = blockIdx.x * 4;
    const int tid = threadIdx.x;
    __shared__ float xs[4][64];

    #pragma unroll
    for (int r = 0; r < 2; r++) {
        int li = r * 128 + tid;
        xs[li >> 6][li & 63] = x[n0 * 64 + li];
    }
    __syncthreads();

    float a1[4] = {0.f, 0.f, 0.f, 0.f};
    float a2[4] = {0.f, 0.f, 0.f, 0.f};
    #pragma unroll 4
    for (int c = 0; c < 64; c++) {
        float wa = W1[c * 128 + tid];
        float wb = W1[(64 + c) * 128 + tid];
        float wd = wa - wb;
        #pragma unroll
        for (int nn = 0; nn < 4; nn++) {
            float xv = xs[nn][c];
            a1[nn] = fmaf(xv, wd, a1[nn]);
            a2[nn] = fmaf(xv, wb, a2[nn]);
        }
    }
    float bb = b1[tid];
    #pragma unroll
    for (int nn = 0; nn < 4; nn++) {
        g_base[(n0 + nn) * 128 + tid] = a1[nn] + bb;
        g_Bv[(n0 + nn) * 128 + tid]  = a2[nn];
    }

    int w = tid >> 5, lane = tid & 31;
    float v = xs[w][lane] * xs[w][lane] + xs[w][lane + 32] * xs[w][lane + 32];
    #pragma unroll
    for (int off = 16; off > 0; off >>= 1)
        v += __shfl_xor_sync(0xffffffffu, v, off);
    if (lane == 0) g_sq[n0 + w] = v;
}

// =================================================================
// fragpack: bf16(hi) of x into mma fragment order (per 128-pt block).
// =================================================================
__global__ void __launch_bounds__(256) fragpack_kernel(const float* __restrict__ x)
{
    __shared__ unsigned sA[4096];
    __shared__ unsigned sB[4096];

    const int blk = blockIdx.x;
    const int tid = threadIdx.x;
    const int rl  = tid >> 1;
    const int c0  = (tid & 1) * 32;

    float v[32];
    const float4* xr = (const float4*)(x + (blk * 128 + rl) * 64 + c0);
    #pragma unroll
    for (int i = 0; i < 8; i++) {
        float4 t = xr[i];
        v[i * 4 + 0] = t.x; v[i * 4 + 1] = t.y;
        v[i * 4 + 2] = t.z; v[i * 4 + 3] = t.w;
    }

    const int mt = rl >> 4, gid = rl & 7, r0 = (rl >> 3) & 1;
    const int nt = rl >> 3;
    const int l  = gid * 4;

    #pragma unroll
    for (int cc = 0; cc < 32; cc += 2) {
        int c = c0 + cc;
        __nv_bfloat16 h0 = __float2bfloat16(v[cc]);
        __nv_bfloat16 h1 = __float2bfloat16(v[cc + 1]);
        unsigned uhi = ((unsigned)__bfloat16_as_ushort(h1) << 16) | __bfloat16_as_ushort(h0);

        int ks = c >> 4, cb = (c >> 1) & 3, r1 = (c >> 3) & 1;
        int la = l + cb;
        int rA = r1 * 2 + r0;
        sA[(ks * 8 + mt) * 128 + la * 4 + rA] = uhi;
        sB[(ks * 16 + nt) * 64 + la * 2 + r1] = uhi;
    }
    __syncthreads();

    uint4* dA = (uint4*)(g_Af + blk * 4096);
    uint4* dB = (uint4*)(g_Bf + blk * 4096);
    const uint4* s4A = (const uint4*)sA;
    const uint4* s4B = (const uint4*)sB;
    #pragma unroll
    for (int i = 0; i < 4; i++) {
        dA[i * 256 + tid] = s4A[i * 256 + tid];
        dB[i * 256 + tid] = s4B[i * 256 + tid];
    }
}

// =================================================================
// tau_kernel: 16th-smallest VALUE over an 8-tile subsample -> g_tau.
// CTA = (qblk, half): 256 CTAs, 2/SM (one wave).  Value-only min/max
// sorting chain (no indices, branch-free, 2 instr/step).
// =================================================================
#define T_OFF_B   4096           // 2 x 4096 u32
#define T_OFF_SQ  12288          // 2 x 128 floats
#define T_OFF_MRG 12544          // 128 x 64 floats
#define T_SM_U32  20736
#define T_SM_BYTES (T_SM_U32 * 4)

// value-only sorted insert: kd ascending, drop max
#define VRIPPLE(kd, dval) do {                                             \
    float _t = (dval);                                                     \
    _Pragma("unroll")                                                      \
    for (int _m = 0; _m < 16; _m++) {                                      \
        float _lo = fminf(kd[_m], _t);                                     \
        _t = fmaxf(kd[_m], _t);                                            \
        kd[_m] = _lo;                                                      \
    }                                                                      \
} while (0)

__device__ __forceinline__ void cp16(unsigned saddr, const void* g)
{
    asm volatile("cp.async.cg.shared.global [%0], [%1], 16;" :: "r"(saddr), "l"(g));
}

__global__ void __launch_bounds__(256, 2) tau_kernel()
{
    extern __shared__ __align__(16) unsigned sm[];
    float* mrgf = (float*)(sm + T_OFF_MRG);

    const int tid  = threadIdx.x;
    const int lane = tid & 31;
    const int wid  = tid >> 5;
    const int g    = lane >> 2;
    const int c    = lane & 3;
    const int qblk = blockIdx.x >> 1;
    const int half = blockIdx.x & 1;
    const int jt0  = half * (STILES / 2);
    const int jt1  = jt0 + STILES / 2;
    const unsigned smbase = (unsigned)__cvta_generic_to_shared(sm);

    {
        const uint4* gA = (const uint4*)(g_Af + qblk * 4096);
        #pragma unroll
        for (int i = 0; i < 4; i++)
            cp16(smbase + (i * 256 + tid) * 16, gA + i * 256 + tid);
        const uint4* gB = (const uint4*)(g_Bf + jt0 * 4096);
        #pragma unroll
        for (int i = 0; i < 4; i++)
            cp16(smbase + (T_OFF_B + (jt0 & 1) * 4096 + i * 1024) * 4 + tid * 16,
                 gB + i * 256 + tid);
        if (tid < 32)
            cp16(smbase + (T_OFF_SQ + (jt0 & 1) * 128) * 4 + tid * 16,
                 g_sq + jt0 * 128 + tid * 4);
    }
    asm volatile("cp.async.commit_group;");

    float kd0[16], kd1[16];
    #pragma unroll
    for (int m = 0; m < 16; m++) { kd0[m] = 1e30f; kd1[m] = 1e30f; }

    for (int jt = jt0; jt < jt1; jt++) {
        const int cur = jt & 1;
        if (jt + 1 < jt1) {
            const uint4* gB = (const uint4*)(g_Bf + (jt + 1) * 4096);
            #pragma unroll
            for (int i = 0; i < 4; i++)
                cp16(smbase + (T_OFF_B + ((jt + 1) & 1) * 4096 + i * 1024) * 4 + tid * 16,
                     gB + i * 256 + tid);
            if (tid < 32)
                cp16(smbase + (T_OFF_SQ + ((jt + 1) & 1) * 128) * 4 + tid * 16,
                     g_sq + (jt + 1) * 128 + tid * 4);
        }
        asm volatile("cp.async.commit_group;");
        asm volatile("cp.async.wait_group 1;");
        __syncthreads();

        unsigned a[4][4];
        #pragma unroll
        for (int ks = 0; ks < 4; ks++) {
            uint4 t = *(const uint4*)(sm + (ks * 8 + wid) * 128 + lane * 4);
            a[ks][0] = t.x; a[ks][1] = t.y; a[ks][2] = t.z; a[ks][3] = t.w;
        }
        const float* sqb = (const float*)(sm + T_OFF_SQ + cur * 128);
        const unsigned* Bb = sm + T_OFF_B + cur * 4096;

        #pragma unroll 4
        for (int ni = 0; ni < 16; ni++) {
            unsigned b[4][2];
            #pragma unroll
            for (int ks = 0; ks < 4; ks++) {
                uint2 t = *(const uint2*)(Bb + (ks * 16 + ni) * 64 + lane * 2);
                b[ks][0] = t.x; b[ks][1] = t.y;
            }
            float acc[4] = {0.f, 0.f, 0.f, 0.f};
            #pragma unroll
            for (int ks = 0; ks < 4; ks++)
                asm volatile(
                    "mma.sync.aligned.m16n8k16.row.col.f32.bf16.bf16.f32 "
                    "{%0,%1,%2,%3}, {%4,%5,%6,%7}, {%8,%9}, {%0,%1,%2,%3};"
                    : "+f"(acc[0]), "+f"(acc[1]), "+f"(acc[2]), "+f"(acc[3])
                    : "r"(a[ks][0]), "r"(a[ks][1]), "r"(a[ks][2]), "r"(a[ks][3]),
                      "r"(b[ks][0]), "r"(b[ks][1]));

            float2 q = *(const float2*)&sqb[ni * 8 + c * 2];
            float d0 = fmaf(0.5f, q.x, -acc[0]);
            float d1 = fmaf(0.5f, q.y, -acc[1]);
            float d2 = fmaf(0.5f, q.x, -acc[2]);
            float d3 = fmaf(0.5f, q.y, -acc[3]);
            if (fminf(d0, d1) < kd0[15]) {
                VRIPPLE(kd0, d0);
                VRIPPLE(kd0, d1);
            }
            if (fminf(d2, d3) < kd1[15]) {
                VRIPPLE(kd1, d2);
                VRIPPLE(kd1, d3);
            }
        }
        __syncthreads();
    }

    // merge 4 sorted lane-lists -> 16th smallest -> g_tau[(q,half)]
    {
        const int rowA = wid * 16 + g;
        #pragma unroll
        for (int m = 0; m < 16; m++) {
            mrgf[rowA * 64 + c * 16 + m] = kd0[m];
            mrgf[(rowA + 8) * 64 + c * 16 + m] = kd1[m];
        }
    }
    __syncthreads();
    if (tid < 128) {
        const float* basep = mrgf + tid * 64;
        int p0 = 0, p1 = 0, p2 = 0, p3 = 0;
        float last = 1e30f;
        #pragma unroll
        for (int m = 0; m < 16; m++) {
            float v0 = basep[p0];
            float v1 = basep[16 + p1];
            float v2 = basep[32 + p2];
            float v3 = basep[48 + p3];
            float mn01 = fminf(v0, v1), mn23 = fminf(v2, v3);
            last = fminf(mn01, mn23);
            if (v0 == last)      p0++;
            else if (v1 == last) p1++;
            else if (v2 == last) p2++;
            else                 p3++;
        }
        g_tau[(qblk * 128 + tid) * 2 + half] = last;
    }
}

// =================================================================
// scan_kernel: full scan, branch-free ballot compaction of d <= tau.
// CTA = (qblk, jslice): 128 queries x 32 tiles. 512 CTAs, ~3/SM.
// Slice s writes candidates into quarter s of g_cand (128 slots).
// =================================================================
#define S_OFF_B   4096           // 2 x 4096 u32
#define S_OFF_SQ  12288          // 2 x 128 floats
#define S_OFF_CNT 12544          // 128 ints
#define S_SM_U32  12672
#define S_SM_BYTES (S_SM_U32 * 4)

__global__ void __launch_bounds__(256, 3) scan_kernel()
{
    extern __shared__ __align__(16) unsigned sm[];
    int* scnt = (int*)(sm + S_OFF_CNT);

    const int tid  = threadIdx.x;
    const int lane = tid & 31;
    const int wid  = tid >> 5;
    const int g    = lane >> 2;
    const int c    = lane & 3;
    const int qblk   = blockIdx.x >> 2;
    const int jslice = blockIdx.x & 3;
    const int jt0 = jslice * JT_PER;
    const unsigned smbase = (unsigned)__cvta_generic_to_shared(sm);

    {
        const uint4* gA = (const uint4*)(g_Af + qblk * 4096);
        #pragma unroll
        for (int i = 0; i < 4; i++)
            cp16(smbase + (i * 256 + tid) * 16, gA + i * 256 + tid);
        const uint4* gB = (const uint4*)(g_Bf + jt0 * 4096);
        #pragma unroll
        for (int i = 0; i < 4; i++)
            cp16(smbase + (S_OFF_B + i * 1024) * 4 + tid * 16, gB + i * 256 + tid);
        if (tid < 32)
            cp16(smbase + S_OFF_SQ * 4 + tid * 16, g_sq + jt0 * 128 + tid * 4);
    }
    asm volatile("cp.async.commit_group;");

    if (tid < 128) scnt[tid] = 0;

    const int rowA = wid * 16 + g;
    const int rowB = rowA + 8;
    const int rowAg = qblk * 128 + rowA;
    const int rowBg = qblk * 128 + rowB;
    const float tg  = fminf(g_tau[rowAg * 2], g_tau[rowAg * 2 + 1]);
    const float tg8 = fminf(g_tau[rowBg * 2], g_tau[rowBg * 2 + 1]);
    const int sh4  = g * 4;
    const int cbase = jslice * 128;

    for (int jt = jt0; jt < jt0 + JT_PER; jt++) {
        const int cur = jt & 1;
        if (jt + 1 < jt0 + JT_PER) {
            const uint4* gB = (const uint4*)(g_Bf + (jt + 1) * 4096);
            #pragma unroll
            for (int i = 0; i < 4; i++)
                cp16(smbase + (S_OFF_B + ((jt + 1) & 1) * 4096 + i * 1024) * 4 + tid * 16,
                     gB + i * 256 + tid);
            if (tid < 32)
                cp16(smbase + (S_OFF_SQ + ((jt + 1) & 1) * 128) * 4 + tid * 16,
                     g_sq + (jt + 1) * 128 + tid * 4);
        }
        asm volatile("cp.async.commit_group;");
        asm volatile("cp.async.wait_group 1;");
        __syncthreads();

        unsigned a[4][4];
        #pragma unroll
        for (int ks = 0; ks < 4; ks++) {
            uint4 t = *(const uint4*)(sm + (ks * 8 + wid) * 128 + lane * 4);
            a[ks][0] = t.x; a[ks][1] = t.y; a[ks][2] = t.z; a[ks][3] = t.w;
        }
        const float* sqb = (const float*)(sm + S_OFF_SQ + cur * 128);
        const unsigned* Bb = sm + S_OFF_B + cur * 4096;

        #pragma unroll 4
        for (int ni = 0; ni < 16; ni++) {
            unsigned b[4][2];
            #pragma unroll
            for (int ks = 0; ks < 4; ks++) {
                uint2 t = *(const uint2*)(Bb + (ks * 16 + ni) * 64 + lane * 2);
                b[ks][0] = t.x; b[ks][1] = t.y;
            }
            float acc[4] = {0.f, 0.f, 0.f, 0.f};
            #pragma unroll
            for (int ks = 0; ks < 4; ks++)
                asm volatile(
                    "mma.sync.aligned.m16n8k16.row.col.f32.bf16.bf16.f32 "
                    "{%0,%1,%2,%3}, {%4,%5,%6,%7}, {%8,%9}, {%0,%1,%2,%3};"
                    : "+f"(acc[0]), "+f"(acc[1]), "+f"(acc[2]), "+f"(acc[3])
                    : "r"(a[ks][0]), "r"(a[ks][1]), "r"(a[ks][2]), "r"(a[ks][3]),
                      "r"(b[ks][0]), "r"(b[ks][1]));

            float2 q = *(const float2*)&sqb[ni * 8 + c * 2];
            float d0 = fmaf(0.5f, q.x, -acc[0]);
            float d1 = fmaf(0.5f, q.y, -acc[1]);
            float d2 = fmaf(0.5f, q.x, -acc[2]);
            float d3 = fmaf(0.5f, q.y, -acc[3]);
            bool c0 = d0 <= tg, c1 = d1 <= tg;
            bool c2 = d2 <= tg8, c3 = d3 <= tg8;
            unsigned bl0 = __ballot_sync(0xffffffffu, c0);
            unsigned bl1 = __ballot_sync(0xffffffffu, c1);
            unsigned bl2 = __ballot_sync(0xffffffffu, c2);
            unsigned bl3 = __ballot_sync(0xffffffffu, c3);
            if (bl0 | bl1 | bl2 | bl3) {       // warp-uniform
                unsigned h0 = (bl0 >> sh4) & 0xFu, h1 = (bl1 >> sh4) & 0xFu;
                unsigned h2 = (bl2 >> sh4) & 0xFu, h3 = (bl3 >> sh4) & 0xFu;
                int cntA = __popc(h0) + __popc(h1);
                int cntB = __popc(h2) + __popc(h3);
                int baseA = 0, baseB = 0;
                if (c == 0 && cntA) baseA = atomicAdd(&scnt[rowA], cntA);
                if (c == 0 && cntB) baseB = atomicAdd(&scnt[rowB], cntB);
                baseA = __shfl_sync(0xffffffffu, baseA, sh4);
                baseB = __shfl_sync(0xffffffffu, baseB, sh4);
                unsigned lm = (1u << c) - 1u;
                int jb = jt * 128 + ni * 8 + c * 2;
                int pA0 = baseA + __popc(h0 & lm);
                int pA1 = baseA + __popc(h0) + __popc(h1 & lm);
                int pB0 = baseB + __popc(h2 & lm);
                int pB1 = baseB + __popc(h2) + __popc(h3 & lm);
                if (c0 && pA0 < 128) g_cand[rowAg * NC + cbase + pA0] = jb;
                if (c1 && pA1 < 128) g_cand[rowAg * NC + cbase + pA1] = jb + 1;
                if (c2 && pB0 < 128) g_cand[rowBg * NC + cbase + pB0] = jb;
                if (c3 && pB1 < 128) g_cand[rowBg * NC + cbase + pB1] = jb + 1;
            }
        }
        __syncthreads();
    }

    if (tid < 128)
        g_cnt[(qblk * 128 + tid) * 4 + jslice] = min(scnt[tid], 128);
}

// =================================================================
// refine: exact fp32 re-score of the candidate set, true top-16.
// 1 query per block, 256 threads; contiguous slots (2 per thread),
// inactive warps skip entirely.
// =================================================================
__global__ void __launch_bounds__(256) refine_kernel(const float* __restrict__ x)
{
    __shared__ float xi[64];
    __shared__ __align__(16) float ss[NC + 4];
    const int tid = threadIdx.x;
    const int q   = blockIdx.x;
    const int c0s = g_cnt[q * 4];
    const int c1s = g_cnt[q * 4 + 1];
    const int c2s = g_cnt[q * 4 + 2];
    const int c3s = g_cnt[q * 4 + 3];
    const int e0 = c0s, e1 = c0s + c1s, e2 = e1 + c2s;
    const int count = e2 + c3s;

    if (tid < 64) xi[tid] = x[q * 64 + tid];
    if (tid < 4)  ss[NC + tid] = 1e30f;
    __syncthreads();

    const int slot0 = tid * 2, slot1 = tid * 2 + 1;
    float s0 = 1e30f, s1 = 1e30f;
    int cj0 = 0, cj1 = 0;
    if (slot0 < count) {
        #pragma unroll
        for (int sl = 0; sl < 2; sl++) {
            int slot = slot0 + sl;
            if (slot < count) {
                int pos;
                if (slot < e0)      pos = slot;
                else if (slot < e1) pos = 128 + (slot - e0);
                else if (slot < e2) pos = 256 + (slot - e1);
                else                pos = 384 + (slot - e2);
                int cj = g_cand[q * NC + pos];
                const float4* xr = (const float4*)(x + cj * 64);
                float dot = 0.f;
                #pragma unroll
                for (int u = 0; u < 16; u++) {
                    float4 v = xr[u];
                    dot = fmaf(xi[u * 4 + 0], v.x, dot);
                    dot = fmaf(xi[u * 4 + 1], v.y, dot);
                    dot = fmaf(xi[u * 4 + 2], v.z, dot);
                    dot = fmaf(xi[u * 4 + 3], v.w, dot);
                }
                float s = fmaf(0.5f, g_sq[cj], -dot);
                if (sl == 0) { s0 = s; cj0 = cj; }
                else         { s1 = s; cj1 = cj; }
            }
        }
    }
    ss[slot0] = s0;
    ss[slot1] = s1;
    __syncthreads();

    if (slot0 < count) {                       // inactive warps skip
        const int nIter = (count + 3) >> 2;
        int rank0 = 0, rank1 = 0;
        #pragma unroll 4
        for (int m4 = 0; m4 < nIter; m4++) {
            float4 v = *(const float4*)&ss[m4 * 4];
            int b0 = m4 * 4;
            rank0 += (v.x < s0) || (v.x == s0 && b0 + 0 < slot0);
            rank0 += (v.y < s0) || (v.y == s0 && b0 + 1 < slot0);
            rank0 += (v.z < s0) || (v.z == s0 && b0 + 2 < slot0);
            rank0 += (v.w < s0) || (v.w == s0 && b0 + 3 < slot0);
            rank1 += (v.x < s1) || (v.x == s1 && b0 + 0 < slot1);
            rank1 += (v.y < s1) || (v.y == s1 && b0 + 1 < slot1);
            rank1 += (v.z < s1) || (v.z == s1 && b0 + 2 < slot1);
            rank1 += (v.w < s1) || (v.w == s1 && b0 + 3 < slot1);
        }
        if (rank0 < KNN) g_idx[q * KNN + rank0] = cj0;
        if (slot1 < count && rank1 < KNN) g_idx[q * KNN + rank1] = cj1;
    }
}

// =================================================================
// aggregate: s = mean_k relu(base + Bv[j_k]);  out = s @ W2 + b2
// 8 points per block, 128 threads (o = tid), W2 read coalesced.
// =================================================================
__global__ void __launch_bounds__(128) aggregate_kernel(
    const float* __restrict__ W2, const float* __restrict__ b2,
    float* __restrict__ out)
{
    const int n0  = blockIdx.x * 8;
    const int tid = threadIdx.x;
    __shared__ float ss[8][128];
    __shared__ int sidx[128];

    sidx[tid] = g_idx[n0 * 16 + tid];
    __syncthreads();

    #pragma unroll
    for (int p = 0; p < 8; p++) {
        float bv  = g_base[(n0 + p) * 128 + tid];
        float acc = 0.f;
        #pragma unroll
        for (int k = 0; k < 16; k++) {
            float v = bv + g_Bv[sidx[p * 16 + k] * 128 + tid];
            acc += fmaxf(v, 0.f);
        }
        ss[p][tid] = acc * (1.0f / 16.0f);
    }
    __syncthreads();

    float r[8];
    float bb = b2[tid];
    #pragma unroll
    for (int p = 0; p < 8; p++) r[p] = bb;

    #pragma unroll 4
    for (int i = 0; i < 128; i++) {
        float w = W2[i * 128 + tid];
        #pragma unroll
        for (int p = 0; p < 8; p++)
            r[p] = fmaf(ss[p][i], w, r[p]);
    }
    #pragma unroll
    for (int p = 0; p < 8; p++)
        out[(n0 + p) * 128 + tid] = r[p];
}

// =================================================================
extern "C" void kernel_launch(void* const* d_in, const int* in_sizes, int n_in,
                              void* d_out, int out_size)
{
    const float* x  = (const float*)d_in[0];
    const float* W1 = (const float*)d_in[1];
    const float* b1 = (const float*)d_in[2];
    const float* W2 = (const float*)d_in[3];
    const float* b2 = (const float*)d_in[4];
    float* out = (float*)d_out;

    cudaFuncSetAttribute(tau_kernel,
                         cudaFuncAttributeMaxDynamicSharedMemorySize, T_SM_BYTES);
    cudaFuncSetAttribute(scan_kernel,
                         cudaFuncAttributeMaxDynamicSharedMemorySize, S_SM_BYTES);

    precompute_kernel<<<NPTS / 4, 128>>>(x, W1, b1);
    fragpack_kernel<<<NBLK, 256>>>(x);
    tau_kernel<<<NBLK * 2, 256, T_SM_BYTES>>>();
    scan_kernel<<<NBLK * JSPLIT, 256, S_SM_BYTES>>>();
    refine_kernel<<<NPTS, 256>>>(x);
    aggregate_kernel<<<NPTS / 8, 128>>>(W2, b2, out);
}

// round 16
// speedup vs baseline: 1.5462x; 1.4772x over previous
#include <cuda_runtime.h>
#include <cuda_bf16.h>
#include <cstdint>

#define NPTS 16384
#define ODIM 128
#define KNN  16
#define NC   512           // candidate buffer per query (2 x 256 halves)
#define NBLK 128           // 16384 / 128
#define STILES 16          // subsample tiles for threshold (j < 2048)
#define JSPLIT 2
#define JT_PER 64

// ---------------- scratch (no allocation allowed) ----------------
__device__ float g_base[NPTS * ODIM];              // x @ (W1a - W1b) + b1
__device__ float g_Bv[NPTS * ODIM];                // x @ W1b
__device__ __align__(16) float g_sq[NPTS];         // |x|^2
__device__ float g_tau[NPTS];                      // per-query threshold
__device__ int   g_idx[NPTS * KNN];                // final knn indices
__device__ int   g_cnt[NPTS * 2];                  // counts per (query, slice)
__device__ int   g_cand[NPTS * NC];                // candidate indices
__device__ __align__(16) unsigned g_Af[NBLK * 4096];  // A fragments (bf16 hi)
__device__ __align__(16) unsigned g_Bf[NBLK * 4096];  // B fragments (bf16 hi)

// =================================================================
// precompute: base, Bv, sq.  4 points per block, 128 threads (o=tid)
// =================================================================
__global__ void __launch_bounds__(128) precompute_kernel(
    const float* __restrict__ x, const float* __restrict__ W1,
    const float* __restrict__ b1)
{
    const int n0  = blockIdx.x * 4;
    const int tid = threadIdx.x;
    __shared__ float xs[4][64];

    #pragma unroll
    for (int r = 0; r < 2; r++) {
        int li = r * 128 + tid;
        xs[li >> 6][li & 63] = x[n0 * 64 + li];
    }
    __syncthreads();

    float a1[4] = {0.f, 0.f, 0.f, 0.f};
    float a2[4] = {0.f, 0.f, 0.f, 0.f};
    #pragma unroll 4
    for (int c = 0; c < 64; c++) {
        float wa = W1[c * 128 + tid];
        float wb = W1[(64 + c) * 128 + tid];
        float wd = wa - wb;
        #pragma unroll
        for (int nn = 0; nn < 4; nn++) {
            float xv = xs[nn][c];
            a1[nn] = fmaf(xv, wd, a1[nn]);
            a2[nn] = fmaf(xv, wb, a2[nn]);
        }
    }
    float bb = b1[tid];
    #pragma unroll
    for (int nn = 0; nn < 4; nn++) {
        g_base[(n0 + nn) * 128 + tid] = a1[nn] + bb;
        g_Bv[(n0 + nn) * 128 + tid]  = a2[nn];
    }

    int w = tid >> 5, lane = tid & 31;
    float v = xs[w][lane] * xs[w][lane] + xs[w][lane + 32] * xs[w][lane + 32];
    #pragma unroll
    for (int off = 16; off > 0; off >>= 1)
        v += __shfl_xor_sync(0xffffffffu, v, off);
    if (lane == 0) g_sq[n0 + w] = v;
}

// =================================================================
// fragpack: bf16(hi) of x into mma fragment order (per 128-pt block).
// =================================================================
__global__ void __launch_bounds__(256) fragpack_kernel(const float* __restrict__ x)
{
    __shared__ unsigned sA[4096];
    __shared__ unsigned sB[4096];

    const int blk = blockIdx.x;
    const int tid = threadIdx.x;
    const int rl  = tid >> 1;
    const int c0  = (tid & 1) * 32;

    float v[32];
    const float4* xr = (const float4*)(x + (blk * 128 + rl) * 64 + c0);
    #pragma unroll
    for (int i = 0; i < 8; i++) {
        float4 t = xr[i];
        v[i * 4 + 0] = t.x; v[i * 4 + 1] = t.y;
        v[i * 4 + 2] = t.z; v[i * 4 + 3] = t.w;
    }

    const int mt = rl >> 4, gid = rl & 7, r0 = (rl >> 3) & 1;
    const int nt = rl >> 3;
    const int l  = gid * 4;

    #pragma unroll
    for (int cc = 0; cc < 32; cc += 2) {
        int c = c0 + cc;
        __nv_bfloat16 h0 = __float2bfloat16(v[cc]);
        __nv_bfloat16 h1 = __float2bfloat16(v[cc + 1]);
        unsigned uhi = ((unsigned)__bfloat16_as_ushort(h1) << 16) | __bfloat16_as_ushort(h0);

        int ks = c >> 4, cb = (c >> 1) & 3, r1 = (c >> 3) & 1;
        int la = l + cb;
        int rA = r1 * 2 + r0;
        sA[(ks * 8 + mt) * 128 + la * 4 + rA] = uhi;
        sB[(ks * 16 + nt) * 64 + la * 2 + r1] = uhi;
    }
    __syncthreads();

    uint4* dA = (uint4*)(g_Af + blk * 4096);
    uint4* dB = (uint4*)(g_Bf + blk * 4096);
    const uint4* s4A = (const uint4*)sA;
    const uint4* s4B = (const uint4*)sB;
    #pragma unroll
    for (int i = 0; i < 4; i++) {
        dA[i * 256 + tid] = s4A[i * 256 + tid];
        dB[i * 256 + tid] = s4B[i * 256 + tid];
    }
}

// =================================================================
// tau_kernel: 16th-smallest VALUE over 16-tile subsample -> g_tau.
// 128 CTAs x 256 threads.  Value-only min/max sorting chain.
// =================================================================
#define T_OFF_B   4096           // 2 x 4096 u32
#define T_OFF_SQ  12288          // 2 x 128 floats
#define T_OFF_MRG 12544          // 128 x 64 floats
#define T_SM_U32  20736
#define T_SM_BYTES (T_SM_U32 * 4)

// value-only sorted insert: kd ascending, drop max
#define VRIPPLE(kd, dval) do {                                             \
    float _t = (dval);                                                     \
    _Pragma("unroll")                                                      \
    for (int _m = 0; _m < 16; _m++) {                                      \
        float _lo = fminf(kd[_m], _t);                                     \
        _t = fmaxf(kd[_m], _t);                                            \
        kd[_m] = _lo;                                                      \
    }                                                                      \
} while (0)

__device__ __forceinline__ void cp16(unsigned saddr, const void* g)
{
    asm volatile("cp.async.cg.shared.global [%0], [%1], 16;" :: "r"(saddr), "l"(g));
}

__global__ void __launch_bounds__(256, 2) tau_kernel()
{
    extern __shared__ __align__(16) unsigned sm[];
    float* mrgf = (float*)(sm + T_OFF_MRG);

    const int tid  = threadIdx.x;
    const int lane = tid & 31;
    const int wid  = tid >> 5;
    const int g    = lane >> 2;
    const int c    = lane & 3;
    const int qblk = blockIdx.x;
    const unsigned smbase = (unsigned)__cvta_generic_to_shared(sm);

    {
        const uint4* gA = (const uint4*)(g_Af + qblk * 4096);
        #pragma unroll
        for (int i = 0; i < 4; i++)
            cp16(smbase + (i * 256 + tid) * 16, gA + i * 256 + tid);
        const uint4* gB = (const uint4*)(g_Bf);
        #pragma unroll
        for (int i = 0; i < 4; i++)
            cp16(smbase + (T_OFF_B + i * 1024) * 4 + tid * 16, gB + i * 256 + tid);
        if (tid < 32)
            cp16(smbase + T_OFF_SQ * 4 + tid * 16, g_sq + tid * 4);
    }
    asm volatile("cp.async.commit_group;");

    float kd0[16], kd1[16];
    #pragma unroll
    for (int m = 0; m < 16; m++) { kd0[m] = 1e30f; kd1[m] = 1e30f; }

    for (int jt = 0; jt < STILES; jt++) {
        const int cur = jt & 1;
        if (jt + 1 < STILES) {
            const uint4* gB = (const uint4*)(g_Bf + (jt + 1) * 4096);
            #pragma unroll
            for (int i = 0; i < 4; i++)
                cp16(smbase + (T_OFF_B + ((jt + 1) & 1) * 4096 + i * 1024) * 4 + tid * 16,
                     gB + i * 256 + tid);
            if (tid < 32)
                cp16(smbase + (T_OFF_SQ + ((jt + 1) & 1) * 128) * 4 + tid * 16,
                     g_sq + (jt + 1) * 128 + tid * 4);
        }
        asm volatile("cp.async.commit_group;");
        asm volatile("cp.async.wait_group 1;");
        __syncthreads();

        unsigned a[4][4];
        #pragma unroll
        for (int ks = 0; ks < 4; ks++) {
            uint4 t = *(const uint4*)(sm + (ks * 8 + wid) * 128 + lane * 4);
            a[ks][0] = t.x; a[ks][1] = t.y; a[ks][2] = t.z; a[ks][3] = t.w;
        }
        const float* sqb = (const float*)(sm + T_OFF_SQ + cur * 128);
        const unsigned* Bb = sm + T_OFF_B + cur * 4096;

        #pragma unroll 4
        for (int ni = 0; ni < 16; ni++) {
            unsigned b[4][2];
            #pragma unroll
            for (int ks = 0; ks < 4; ks++) {
                uint2 t = *(const uint2*)(Bb + (ks * 16 + ni) * 64 + lane * 2);
                b[ks][0] = t.x; b[ks][1] = t.y;
            }
            float acc[4] = {0.f, 0.f, 0.f, 0.f};
            #pragma unroll
            for (int ks = 0; ks < 4; ks++)
                asm volatile(
                    "mma.sync.aligned.m16n8k16.row.col.f32.bf16.bf16.f32 "
                    "{%0,%1,%2,%3}, {%4,%5,%6,%7}, {%8,%9}, {%0,%1,%2,%3};"
                    : "+f"(acc[0]), "+f"(acc[1]), "+f"(acc[2]), "+f"(acc[3])
                    : "r"(a[ks][0]), "r"(a[ks][1]), "r"(a[ks][2]), "r"(a[ks][3]),
                      "r"(b[ks][0]), "r"(b[ks][1]));

            float2 q = *(const float2*)&sqb[ni * 8 + c * 2];
            float d0 = fmaf(0.5f, q.x, -acc[0]);
            float d1 = fmaf(0.5f, q.y, -acc[1]);
            float d2 = fmaf(0.5f, q.x, -acc[2]);
            float d3 = fmaf(0.5f, q.y, -acc[3]);
            if (fminf(d0, d1) < kd0[15]) {
                VRIPPLE(kd0, d0);
                VRIPPLE(kd0, d1);
            }
            if (fminf(d2, d3) < kd1[15]) {
                VRIPPLE(kd1, d2);
                VRIPPLE(kd1, d3);
            }
        }
        __syncthreads();
    }

    // merge 4 sorted lane-lists -> 16th smallest -> g_tau
    {
        const int rowA = wid * 16 + g;
        #pragma unroll
        for (int m = 0; m < 16; m++) {
            mrgf[rowA * 64 + c * 16 + m] = kd0[m];
            mrgf[(rowA + 8) * 64 + c * 16 + m] = kd1[m];
        }
    }
    __syncthreads();
    if (tid < 128) {
        const float* basep = mrgf + tid * 64;
        int p0 = 0, p1 = 0, p2 = 0, p3 = 0;
        float last = 1e30f;
        #pragma unroll
        for (int m = 0; m < 16; m++) {
            float v0 = basep[p0];
            float v1 = basep[16 + p1];
            float v2 = basep[32 + p2];
            float v3 = basep[48 + p3];
            float mn01 = fminf(v0, v1), mn23 = fminf(v2, v3);
            last = fminf(mn01, mn23);
            if (v0 == last)      p0++;
            else if (v1 == last) p1++;
            else if (v2 == last) p2++;
            else                 p3++;
        }
        g_tau[qblk * 128 + tid] = last;
    }
}

// =================================================================
// scan_kernel: full scan; per-ni bitmask accumulate, per-tile atomic
// flush (buffer order irrelevant -> refine re-scores exactly).
// CTA = (qblk, jslice): 128 queries x 64 tiles. 256 CTAs.
// Slice s writes candidates into half s of g_cand (256 slots).
// =================================================================
#define S_OFF_B   4096           // 2 x 4096 u32
#define S_OFF_SQ  12288          // 2 x 128 floats
#define S_OFF_CNT 12544          // 128 ints
#define S_SM_U32  12672
#define S_SM_BYTES (S_SM_U32 * 4)

__global__ void __launch_bounds__(256, 2) scan_kernel()
{
    extern __shared__ __align__(16) unsigned sm[];
    int* scnt = (int*)(sm + S_OFF_CNT);

    const int tid  = threadIdx.x;
    const int lane = tid & 31;
    const int wid  = tid >> 5;
    const int g    = lane >> 2;
    const int c    = lane & 3;
    const int qblk   = blockIdx.x >> 1;
    const int jslice = blockIdx.x & 1;
    const int jt0 = jslice * JT_PER;
    const unsigned smbase = (unsigned)__cvta_generic_to_shared(sm);

    {
        const uint4* gA = (const uint4*)(g_Af + qblk * 4096);
        #pragma unroll
        for (int i = 0; i < 4; i++)
            cp16(smbase + (i * 256 + tid) * 16, gA + i * 256 + tid);
        const uint4* gB = (const uint4*)(g_Bf + jt0 * 4096);
        #pragma unroll
        for (int i = 0; i < 4; i++)
            cp16(smbase + (S_OFF_B + (jt0 & 1) * 4096 + i * 1024) * 4 + tid * 16,
                 gB + i * 256 + tid);
        if (tid < 32)
            cp16(smbase + (S_OFF_SQ + (jt0 & 1) * 128) * 4 + tid * 16,
                 g_sq + jt0 * 128 + tid * 4);
    }
    asm volatile("cp.async.commit_group;");

    if (tid < 128) scnt[tid] = 0;

    const int rowA = wid * 16 + g;
    const int rowB = rowA + 8;
    const int rowAg = qblk * 128 + rowA;
    const int rowBg = qblk * 128 + rowB;
    const float tg  = g_tau[rowAg];
    const float tg8 = g_tau[rowBg];
    const int cbase = jslice * 256;

    for (int jt = jt0; jt < jt0 + JT_PER; jt++) {
        const int cur = jt & 1;
        if (jt + 1 < jt0 + JT_PER) {
            const uint4* gB = (const uint4*)(g_Bf + (jt + 1) * 4096);
            #pragma unroll
            for (int i = 0; i < 4; i++)
                cp16(smbase + (S_OFF_B + ((jt + 1) & 1) * 4096 + i * 1024) * 4 + tid * 16,
                     gB + i * 256 + tid);
            if (tid < 32)
                cp16(smbase + (S_OFF_SQ + ((jt + 1) & 1) * 128) * 4 + tid * 16,
                     g_sq + (jt + 1) * 128 + tid * 4);
        }
        asm volatile("cp.async.commit_group;");
        asm volatile("cp.async.wait_group 1;");
        __syncthreads();

        unsigned a[4][4];
        #pragma unroll
        for (int ks = 0; ks < 4; ks++) {
            uint4 t = *(const uint4*)(sm + (ks * 8 + wid) * 128 + lane * 4);
            a[ks][0] = t.x; a[ks][1] = t.y; a[ks][2] = t.z; a[ks][3] = t.w;
        }
        const float* sqb = (const float*)(sm + S_OFF_SQ + cur * 128);
        const unsigned* Bb = sm + S_OFF_B + cur * 4096;

        unsigned m0 = 0, m1 = 0;
        #pragma unroll 4
        for (int ni = 0; ni < 16; ni++) {
            unsigned b[4][2];
            #pragma unroll
            for (int ks = 0; ks < 4; ks++) {
                uint2 t = *(const uint2*)(Bb + (ks * 16 + ni) * 64 + lane * 2);
                b[ks][0] = t.x; b[ks][1] = t.y;
            }
            float acc[4] = {0.f, 0.f, 0.f, 0.f};
            #pragma unroll
            for (int ks = 0; ks < 4; ks++)
                asm volatile(
                    "mma.sync.aligned.m16n8k16.row.col.f32.bf16.bf16.f32 "
                    "{%0,%1,%2,%3}, {%4,%5,%6,%7}, {%8,%9}, {%0,%1,%2,%3};"
                    : "+f"(acc[0]), "+f"(acc[1]), "+f"(acc[2]), "+f"(acc[3])
                    : "r"(a[ks][0]), "r"(a[ks][1]), "r"(a[ks][2]), "r"(a[ks][3]),
                      "r"(b[ks][0]), "r"(b[ks][1]));

            float2 q = *(const float2*)&sqb[ni * 8 + c * 2];
            float d0 = fmaf(0.5f, q.x, -acc[0]);
            float d1 = fmaf(0.5f, q.y, -acc[1]);
            float d2 = fmaf(0.5f, q.x, -acc[2]);
            float d3 = fmaf(0.5f, q.y, -acc[3]);
            m0 |= (d0 <= tg)  ? (1u << (2 * ni)) : 0u;
            m0 |= (d1 <= tg)  ? (2u << (2 * ni)) : 0u;
            m1 |= (d2 <= tg8) ? (1u << (2 * ni)) : 0u;
            m1 |= (d3 <= tg8) ? (2u << (2 * ni)) : 0u;
        }

        // ---- flush hits (rare): decode bits, atomic slot, store ----
        const int jbase = jt * 128 + c * 2;
        while (m0) {
            int b = __ffs(m0) - 1; m0 &= m0 - 1;
            int j = jbase + ((b >> 1) << 3) + (b & 1);
            int p = atomicAdd(&scnt[rowA], 1);
            if (p < 256) g_cand[rowAg * NC + cbase + p] = j;
        }
        while (m1) {
            int b = __ffs(m1) - 1; m1 &= m1 - 1;
            int j = jbase + ((b >> 1) << 3) + (b & 1);
            int p = atomicAdd(&scnt[rowB], 1);
            if (p < 256) g_cand[rowBg * NC + cbase + p] = j;
        }
        __syncthreads();
    }

    if (tid < 128)
        g_cnt[(qblk * 128 + tid) * 2 + jslice] = min(scnt[tid], 256);
}

// =================================================================
// refine: exact fp32 re-score of the candidate set, true top-16.
// 1 query per block, 256 threads; contiguous slots (2 per thread),
// inactive warps skip entirely.   (R13-proven)
// =================================================================
__global__ void __launch_bounds__(256) refine_kernel(const float* __restrict__ x)
{
    __shared__ float xi[64];
    __shared__ __align__(16) float ss[NC + 4];
    const int tid = threadIdx.x;
    const int q   = blockIdx.x;
    const int cnt0 = g_cnt[q * 2];
    const int cnt1 = g_cnt[q * 2 + 1];
    const int count = cnt0 + cnt1;

    if (tid < 64) xi[tid] = x[q * 64 + tid];
    if (tid < 4)  ss[NC + tid] = 1e30f;
    __syncthreads();

    const int slot0 = tid * 2, slot1 = tid * 2 + 1;
    float s0 = 1e30f, s1 = 1e30f;
    int cj0 = 0, cj1 = 0;
    if (slot0 < count) {
        #pragma unroll
        for (int sl = 0; sl < 2; sl++) {
            int slot = slot0 + sl;
            if (slot < count) {
                int pos = (slot < cnt0) ? slot : (256 + slot - cnt0);
                int cj = g_cand[q * NC + pos];
                const float4* xr = (const float4*)(x + cj * 64);
                float dot = 0.f;
                #pragma unroll
                for (int u = 0; u < 16; u++) {
                    float4 v = xr[u];
                    dot = fmaf(xi[u * 4 + 0], v.x, dot);
                    dot = fmaf(xi[u * 4 + 1], v.y, dot);
                    dot = fmaf(xi[u * 4 + 2], v.z, dot);
                    dot = fmaf(xi[u * 4 + 3], v.w, dot);
                }
                float s = fmaf(0.5f, g_sq[cj], -dot);
                if (sl == 0) { s0 = s; cj0 = cj; }
                else         { s1 = s; cj1 = cj; }
            }
        }
    }
    ss[slot0] = s0;
    ss[slot1] = s1;
    __syncthreads();

    if (slot0 < count) {                       // inactive warps skip
        const int nIter = (count + 3) >> 2;
        int rank0 = 0, rank1 = 0;
        #pragma unroll 4
        for (int m4 = 0; m4 < nIter; m4++) {
            float4 v = *(const float4*)&ss[m4 * 4];
            int b0 = m4 * 4;
            rank0 += (v.x < s0) || (v.x == s0 && b0 + 0 < slot0);
            rank0 += (v.y < s0) || (v.y == s0 && b0 + 1 < slot0);
            rank0 += (v.z < s0) || (v.z == s0 && b0 + 2 < slot0);
            rank0 += (v.w < s0) || (v.w == s0 && b0 + 3 < slot0);
            rank1 += (v.x < s1) || (v.x == s1 && b0 + 0 < slot1);
            rank1 += (v.y < s1) || (v.y == s1 && b0 + 1 < slot1);
            rank1 += (v.z < s1) || (v.z == s1 && b0 + 2 < slot1);
            rank1 += (v.w < s1) || (v.w == s1 && b0 + 3 < slot1);
        }
        if (rank0 < KNN) g_idx[q * KNN + rank0] = cj0;
        if (slot1 < count && rank1 < KNN) g_idx[q * KNN + rank1] = cj1;
    }
}

// =================================================================
// aggregate: s = mean_k relu(base + Bv[j_k]);  out = s @ W2 + b2
// 8 points per block, 128 threads (o = tid), W2 read coalesced.
// =================================================================
__global__ void __launch_bounds__(128) aggregate_kernel(
    const float* __restrict__ W2, const float* __restrict__ b2,
    float* __restrict__ out)
{
    const int n0  = blockIdx.x * 8;
    const int tid = threadIdx.x;
    __shared__ float ss[8][128];
    __shared__ int sidx[128];

    sidx[tid] = g_idx[n0 * 16 + tid];
    __syncthreads();

    #pragma unroll
    for (int p = 0; p < 8; p++) {
        float bv  = g_base[(n0 + p) * 128 + tid];
        float acc = 0.f;
        #pragma unroll
        for (int k = 0; k < 16; k++) {
            float v = bv + g_Bv[sidx[p * 16 + k] * 128 + tid];
            acc += fmaxf(v, 0.f);
        }
        ss[p][tid] = acc * (1.0f / 16.0f);
    }
    __syncthreads();

    float r[8];
    float bb = b2[tid];
    #pragma unroll
    for (int p = 0; p < 8; p++) r[p] = bb;

    #pragma unroll 4
    for (int i = 0; i < 128; i++) {
        float w = W2[i * 128 + tid];
        #pragma unroll
        for (int p = 0; p < 8; p++)
            r[p] = fmaf(ss[p][i], w, r[p]);
    }
    #pragma unroll
    for (int p = 0; p < 8; p++)
        out[(n0 + p) * 128 + tid] = r[p];
}

// =================================================================
extern "C" void kernel_launch(void* const* d_in, const int* in_sizes, int n_in,
                              void* d_out, int out_size)
{
    const float* x  = (const float*)d_in[0];
    const float* W1 = (const float*)d_in[1];
    const float* b1 = (const float*)d_in[2];
    const float* W2 = (const float*)d_in[3];
    const float* b2 = (const float*)d_in[4];
    float* out = (float*)d_out;

    cudaFuncSetAttribute(tau_kernel,
                         cudaFuncAttributeMaxDynamicSharedMemorySize, T_SM_BYTES);
    cudaFuncSetAttribute(scan_kernel,
                         cudaFuncAttributeMaxDynamicSharedMemorySize, S_SM_BYTES);

    precompute_kernel<<<NPTS / 4, 128>>>(x, W1, b1);
    fragpack_kernel<<<NBLK, 256>>>(x);
    tau_kernel<<<NBLK, 256, T_SM_BYTES>>>();
    scan_kernel<<<NBLK * JSPLIT, 256, S_SM_BYTES>>>();
    refine_kernel<<<NPTS, 256>>>(x);
    aggregate_kernel<<<NPTS / 8, 128>>>(W2, b2, out);
}